// round 14
// baseline (speedup 1.0000x reference)
#include <cuda_runtime.h>

#define CDIM 3755
#define NV 938              // (CDIM - h) >> 2 == 938 for every h in 0..3
#define RDIM 214
#define SDIM 13
#define SCBDIM 30
#define STDIM 6
#define HDIM 64
#define KTOP 20
#define CAP 512
#define NT 256
#define NEGF 3.4e38f
#define THR0 2.2f

__device__ __forceinline__ unsigned f2key(float x) {
    unsigned u = __float_as_uint(x);
    return (u & 0x80000000u) ? ~u : (u | 0x80000000u);
}
__device__ __forceinline__ float key2f(unsigned k) {
    return __uint_as_float((k & 0x80000000u) ? (k & 0x7FFFFFFFu) : ~k);
}
__device__ __forceinline__ unsigned long long packvi(float v, int j) {
    return ((unsigned long long)f2key(v) << 32) | (unsigned)(0x7FFFFFFF - j);
}
__device__ __forceinline__ unsigned su32(const void* p) {
    unsigned a;
    asm("{ .reg .u64 t; cvta.to.shared.u64 t, %1; cvt.u32.u64 %0, t; }" : "=r"(a) : "l"(p));
    return a;
}
// mbarrier wait with HW-sleep suspend hint
__device__ __forceinline__ void mbar_wait(unsigned mb) {
    asm volatile(
        "{\n\t.reg .pred P;\n\t"
        "WAIT_%=: mbarrier.try_wait.parity.shared.b64 P, [%0], 0, 0x989680;\n\t"
        "@P bra.uni DONE_%=;\n\t"
        "bra.uni WAIT_%=;\n\t"
        "DONE_%=:\n\t}"
        :: "r"(mb) : "memory");
}

__global__ void __launch_bounds__(NT) rerank_kernel(
    const float* __restrict__ charL, const float* __restrict__ radL,
    const float* __restrict__ structL, const float* __restrict__ scL,
    const float* __restrict__ styL, const int* __restrict__ rmask,
    const int* __restrict__ slab, const int* __restrict__ sclab,
    const float* __restrict__ sig, const float* __restrict__ W1,
    const float* __restrict__ b1, const float* __restrict__ W2,
    const float* __restrict__ b2, const float* __restrict__ rwp,
    float* __restrict__ out)
{
    __shared__ __align__(128) float4 srow4[NV];     // TMA-loaded middle of the row
    __shared__ float shHT[8];                        // head [0..3], tail [4..7]
    __shared__ __align__(8) unsigned long long s_mbar;
    __shared__ unsigned long long cpack[CAP];
    __shared__ float rps[RDIM];
    __shared__ __align__(16) float4 wpack[HDIM * 2]; // {W1[0..3][j]} {W1[4..5][j],b1[j],W2[j]}
    __shared__ float sprob[SDIM], predn[STDIM];
    __shared__ float feat6[KTOP][6];
    __shared__ int tIdx[KTOP];
    __shared__ float tVal[KTOP];
    __shared__ float reds[8], redt[8], redm[8];
    __shared__ unsigned long long red64[8];
    __shared__ unsigned long long s_prev;
    __shared__ float s_b2, s_rw;
    __shared__ int s_ncand, s_spred;

    float* srow = (float*)srow4;
    const int b = blockIdx.x;
    const int tid = threadIdx.x, lane = tid & 31, wid = tid >> 5;

    const float* row = charL + (size_t)b * CDIM;
    float* orow = out + (size_t)b * CDIM;
    const int h = (4 - (int)(((size_t)row >> 2) & 3)) & 3;
    const int tl = 3 - h;
    const int ho = (4 - (int)(((size_t)orow >> 2) & 3)) & 3;

    // ---- init: packed weights + mbarrier ----
    if (tid < HDIM) {
        float4 a, bb;
        a.x = W1[tid]; a.y = W1[HDIM + tid]; a.z = W1[2 * HDIM + tid]; a.w = W1[3 * HDIM + tid];
        bb.x = W1[4 * HDIM + tid]; bb.y = W1[5 * HDIM + tid]; bb.z = b1[tid]; bb.w = W2[tid];
        wpack[tid * 2] = a; wpack[tid * 2 + 1] = bb;
    }
    if (tid == 0) {
        s_b2 = b2[0]; s_rw = rwp[0]; s_ncand = 0;
        asm volatile("mbarrier.init.shared.b64 [%0], 1;" :: "r"(su32(&s_mbar)) : "memory");
    }
    __syncthreads();

    // ---- issue TMA bulk load of the aligned middle ----
    if (tid == 0) {
        unsigned mb = su32(&s_mbar);
        asm volatile("mbarrier.arrive.expect_tx.shared.b64 _, [%0], %1;"
                     :: "r"(mb), "r"(NV * 16) : "memory");
        asm volatile("cp.async.bulk.shared::cta.global.mbarrier::complete_tx::bytes "
                     "[%0], [%1], %2, [%3];"
                     :: "r"(su32(srow4)), "l"(row + h), "r"(NV * 16), "r"(mb) : "memory");
    }

    // ---- head/tail scalars: load + copy-out + stash in smem ----
    float seHT = 0.f;
    if (wid == 0 && lane < h) {
        float v = row[lane]; shHT[lane] = v; orow[lane] = v; seHT = __expf(v);
    }
    if (wid == 1 && lane < tl) {
        int j = h + 4 * NV + lane;
        float v = row[j]; shHT[4 + lane] = v; orow[j] = v; seHT = __expf(v);
    }

    // ---- radical sigmoid + total (overlaps TMA flight) ----
    float tp = 0.f;
    if (tid < RDIM) {
        float p = 1.f / (1.f + __expf(-radL[(size_t)b * RDIM + tid]));
        rps[tid] = p; tp = p;
    }
    // side tasks on distinct warps
    if (tid == 65) {
        const float* st = structL + (size_t)b * SDIM;
        float m = st[0]; float e[SDIM];
        for (int i = 1; i < SDIM; i++) m = fmaxf(m, st[i]);
        float s = 0.f;
        for (int i = 0; i < SDIM; i++) { e[i] = __expf(st[i] - m); s += e[i]; }
        float inv = 1.f / s;
        for (int i = 0; i < SDIM; i++) sprob[i] = e[i] * inv;
    }
    if (tid == 97) {
        const float* sc = scL + (size_t)b * SCBDIM;
        float m = sc[0]; int mi = 0;
        for (int i = 1; i < SCBDIM; i++) { float vv = sc[i]; if (vv > m) { m = vv; mi = i; } }
        s_spred = mi;
    }
    if (tid == 129) {
        const float* sy = styL + (size_t)b * STDIM;
        float vv[STDIM]; float n2 = 0.f;
        for (int i = 0; i < STDIM; i++) { vv[i] = sy[i]; n2 += vv[i] * vv[i]; }
        float n = fmaxf(sqrtf(n2), 1e-12f);
        for (int i = 0; i < STDIM; i++) predn[i] = vv[i] / n;
    }

    // ---- wait for TMA load completion ----
    mbar_wait(su32(&s_mbar));

    // ---- fused sweep: unshifted expsum + order-free threshold collect ----
    float se = seHT;
    const float t0 = THR0;
    #pragma unroll
    for (int u = 0; u < 4; u++) {
        int i = tid + u * NT;
        float4 w;
        if (u < 3 || i < NV) {
            w = srow4[i];
            se += __expf(w.x) + __expf(w.y) + __expf(w.z) + __expf(w.w);
        } else { w.x = w.y = w.z = w.w = -NEGF; }
        int c = (w.x >= t0) + (w.y >= t0) + (w.z >= t0) + (w.w >= t0);
        if (c) {
            int pos = atomicAdd(&s_ncand, c);
            int j0 = h + 4 * i;
            if (w.x >= t0) { if (pos < CAP) cpack[pos] = packvi(w.x, j0); pos++; }
            if (w.y >= t0) { if (pos < CAP) cpack[pos] = packvi(w.y, j0 + 1); pos++; }
            if (w.z >= t0) { if (pos < CAP) cpack[pos] = packvi(w.z, j0 + 2); pos++; }
            if (w.w >= t0) { if (pos < CAP) cpack[pos] = packvi(w.w, j0 + 3); }
        }
    }
    // head/tail candidates
    if (wid == 0 && lane < h) {
        float v = shHT[lane];
        if (v >= t0) { int pos = atomicAdd(&s_ncand, 1); if (pos < CAP) cpack[pos] = packvi(v, lane); }
    }
    if (wid == 1 && lane < tl) {
        float v = shHT[4 + lane];
        if (v >= t0) { int pos = atomicAdd(&s_ncand, 1); if (pos < CAP) cpack[pos] = packvi(v, h + 4 * NV + lane); }
    }
    #pragma unroll
    for (int o = 16; o; o >>= 1) {
        se += __shfl_xor_sync(~0u, se, o);
        tp += __shfl_xor_sync(~0u, tp, o);
    }
    if (lane == 0) { reds[wid] = se; redt[wid] = tp; }
    __syncthreads();

    // all threads compute the block sums directly (broadcast LDS; no tid0 round-trip)
    float ssum = 0.f, total = 0.f;
    #pragma unroll
    for (int w = 0; w < 8; w++) { ssum += reds[w]; total += redt[w]; }
    float shiftv = 0.f;
    int nc = s_ncand;

    // ---- guard: expsum overflow/underflow (never taken for sane logits) ----
    if (isinf(ssum) || isnan(ssum) || ssum < 1e-30f) {
        float mx = -NEGF;
        for (int k = tid; k < 4 * NV; k += NT) mx = fmaxf(mx, srow[k]);
        if (tid < h) mx = fmaxf(mx, shHT[tid]);
        if (tid >= 32 && tid - 32 < tl) mx = fmaxf(mx, shHT[4 + tid - 32]);
        #pragma unroll
        for (int o = 16; o; o >>= 1) mx = fmaxf(mx, __shfl_xor_sync(~0u, mx, o));
        if (lane == 0) redm[wid] = mx;
        __syncthreads();
        shiftv = redm[0];
        #pragma unroll
        for (int w = 1; w < 8; w++) shiftv = fmaxf(shiftv, redm[w]);
        float se2 = 0.f;
        for (int k = tid; k < 4 * NV; k += NT) se2 += __expf(srow[k] - shiftv);
        if (tid < h) se2 += __expf(shHT[tid] - shiftv);
        if (tid >= 32 && tid - 32 < tl) se2 += __expf(shHT[4 + tid - 32] - shiftv);
        #pragma unroll
        for (int o = 16; o; o >>= 1) se2 += __shfl_xor_sync(~0u, se2, o);
        if (lane == 0) reds[wid] = se2;
        __syncthreads();
        ssum = 0.f;
        #pragma unroll
        for (int w = 0; w < 8; w++) ssum += reds[w];
    }

    // ---- retry with lower threshold (rare) ----
    float t = t0;
    while (nc < KTOP) {
        __syncthreads();
        if (tid == 0) s_ncand = 0;
        t -= 1.5f;
        __syncthreads();
        for (int base_k = 0; base_k < 4 * NV; base_k += NT) {
            int k = base_k + tid;
            float v = (k < 4 * NV) ? srow[k] : -NEGF;
            if (v >= t) {
                int pos = atomicAdd(&s_ncand, 1);
                if (pos < CAP) cpack[pos] = packvi(v, h + k);
            }
        }
        if (wid == 0 && lane < h) {
            float v = shHT[lane];
            if (v >= t) { int pos = atomicAdd(&s_ncand, 1); if (pos < CAP) cpack[pos] = packvi(v, lane); }
        }
        if (wid == 1 && lane < tl) {
            float v = shHT[4 + lane];
            if (v >= t) { int pos = atomicAdd(&s_ncand, 1); if (pos < CAP) cpack[pos] = packvi(v, h + 4 * NV + lane); }
        }
        __syncthreads();
        nc = s_ncand;
    }

    // ---- selection: parallel rank (ties: lower index wins, encoded in pack) ----
    if (nc <= NT) {
        if (tid - lane < nc) {
            unsigned long long p0 = (tid < nc) ? cpack[tid] : 0ull;
            int r0 = 0;
            #pragma unroll 4
            for (int j = 0; j < nc; j++) r0 += (cpack[j] > p0);
            if (tid < nc && r0 < KTOP) {
                tIdx[r0] = 0x7FFFFFFF - (int)(p0 & 0xFFFFFFFFu);
                tVal[r0] = key2f((unsigned)(p0 >> 32));
            }
        }
    } else if (nc <= CAP) {
        unsigned long long p0 = cpack[tid];
        unsigned long long p1 = (tid + NT < nc) ? cpack[tid + NT] : 0ull;
        int r0 = 0, r1 = 0;
        for (int j = 0; j < nc; j++) {
            unsigned long long q = cpack[j];
            r0 += (q > p0); r1 += (q > p1);
        }
        if (r0 < KTOP) {
            tIdx[r0] = 0x7FFFFFFF - (int)(p0 & 0xFFFFFFFFu);
            tVal[r0] = key2f((unsigned)(p0 >> 32));
        }
        if (tid + NT < nc && r1 < KTOP) {
            tIdx[r1] = 0x7FFFFFFF - (int)(p1 & 0xFFFFFFFFu);
            tVal[r1] = key2f((unsigned)(p1 >> 32));
        }
    } else {
        // robust fallback (adversarial only): 20 rounds of block argmax over smem
        unsigned long long prev = ~0ull;
        for (int k = 0; k < KTOP; k++) {
            unsigned long long best = 0ull;
            for (int kk = tid; kk < 4 * NV; kk += NT) {
                unsigned long long p = packvi(srow[kk], h + kk);
                if (p < prev && p > best) best = p;
            }
            if (tid < h) { unsigned long long p = packvi(shHT[tid], tid); if (p < prev && p > best) best = p; }
            if (tid >= 32 && tid - 32 < tl) {
                unsigned long long p = packvi(shHT[4 + tid - 32], h + 4 * NV + tid - 32);
                if (p < prev && p > best) best = p;
            }
            #pragma unroll
            for (int o = 16; o; o >>= 1) {
                unsigned long long q = __shfl_xor_sync(~0u, best, o);
                if (q > best) best = q;
            }
            if (lane == 0) red64[wid] = best;
            __syncthreads();
            if (tid == 0) {
                unsigned long long m = red64[0];
                for (int w = 1; w < 8; w++) if (red64[w] > m) m = red64[w];
                tIdx[k] = 0x7FFFFFFF - (int)(m & 0xFFFFFFFFu);
                tVal[k] = key2f((unsigned)(m >> 32));
                s_prev = m;
            }
            __syncthreads();
            prev = s_prev;
        }
    }
    __syncthreads();

    // ---- features: 8-lane groups for radical dot; threads 160.. do scalars ----
    const int g = tid >> 3, gl = tid & 7;
    if (g < KTOP) {
        int c = tIdx[g];
        const int2* m2 = (const int2*)(rmask + (size_t)c * RDIM);
        float det = 0.f; int cnt = 0;
        for (int r = gl; r < RDIM / 2; r += 8) {
            int2 mm = m2[r];
            det = fmaf((float)mm.x, rps[2 * r], det);
            det = fmaf((float)mm.y, rps[2 * r + 1], det);
            cnt += mm.x + mm.y;
        }
        #pragma unroll
        for (int o = 4; o; o >>= 1) {
            det += __shfl_xor_sync(~0u, det, o);
            cnt += __shfl_xor_sync(~0u, cnt, o);
        }
        if (gl == 0) {
            feat6[g][0] = det / fmaxf((float)cnt, 1.f);
            feat6[g][1] = (total - det) / fmaxf(total, 1e-6f);
        }
    }
    if (tid >= 160 && tid < 160 + KTOP) {
        int k = tid - 160;
        int c = tIdx[k];
        feat6[k][2] = sprob[slab[c]];
        feat6[k][3] = fabsf((float)(s_spred - sclab[c])) * (1.f / 29.f);
        const float* s6 = sig + (size_t)c * STDIM;
        float n2 = 0.f, dd = 0.f;
        #pragma unroll
        for (int i = 0; i < STDIM; i++) {
            float vv = s6[i];
            n2 += vv * vv;
            dd += predn[i] * vv;
        }
        float nrm = sqrtf(n2);
        feat6[k][4] = (nrm > 1e-6f) ? dd / fmaxf(nrm, 1e-12f) : 0.f;
        feat6[k][5] = __expf(tVal[k] - shiftv) / ssum;
    }
    __syncthreads();

    // ---- MLP 6->64->1 via packed weights; patch scores into smem/global ----
    if (g < KTOP) {
        float f0 = feat6[g][0], f1 = feat6[g][1], f2 = feat6[g][2];
        float f3 = feat6[g][3], f4 = feat6[g][4], f5 = feat6[g][5];
        float score = 0.f;
        #pragma unroll
        for (int u = 0; u < 8; u++) {
            int j = gl + u * 8;
            float4 a = wpack[j * 2], bb = wpack[j * 2 + 1];
            float hh = bb.z + f0 * a.x + f1 * a.y + f2 * a.z + f3 * a.w
                     + f4 * bb.x + f5 * bb.y;
            score += fmaxf(hh, 0.f) * bb.w;
        }
        #pragma unroll
        for (int o = 4; o; o >>= 1) score += __shfl_xor_sync(~0u, score, o);
        if (gl == 0) {
            int idx = tIdx[g];
            float comb = tVal[g] + s_rw * (score + s_b2);
            if (idx >= h && idx < h + 4 * NV) srow[idx - h] = comb;
            else orow[idx] = comb;       // head/tail patch (ordered after copy by barriers)
        }
    }
    __syncthreads();

    // ---- write the middle back: TMA bulk store (or scalar fallback) ----
    if (ho == h) {
        if (tid == 0) {
            asm volatile("fence.proxy.async.shared::cta;" ::: "memory");
            asm volatile("cp.async.bulk.global.shared::cta.bulk_group [%0], [%1], %2;"
                         :: "l"(orow + h), "r"(su32(srow4)), "r"(NV * 16) : "memory");
            asm volatile("cp.async.bulk.commit_group;" ::: "memory");
            asm volatile("cp.async.bulk.wait_group 0;" ::: "memory");
        }
    } else {
        // out row misaligned vs in row (not expected with cudaMalloc bases)
        for (int k = tid; k < 4 * NV; k += NT) orow[h + k] = srow[k];
    }
}

extern "C" void kernel_launch(void* const* d_in, const int* in_sizes, int n_in,
                              void* d_out, int out_size) {
    (void)n_in; (void)out_size;
    int Bn = in_sizes[0] / CDIM;
    rerank_kernel<<<Bn, NT>>>(
        (const float*)d_in[0],  (const float*)d_in[1],  (const float*)d_in[2],
        (const float*)d_in[3],  (const float*)d_in[4],  (const int*)d_in[5],
        (const int*)d_in[6],    (const int*)d_in[7],    (const float*)d_in[8],
        (const float*)d_in[9],  (const float*)d_in[10], (const float*)d_in[11],
        (const float*)d_in[12], (const float*)d_in[13], (float*)d_out);
}

// round 15
// speedup vs baseline: 1.2857x; 1.2857x over previous
#include <cuda_runtime.h>

#define CDIM 3755
#define NV 938              // (CDIM - h) >> 2 == 938 for every h in 0..3
#define RDIM 214
#define SDIM 13
#define SCBDIM 30
#define STDIM 6
#define HDIM 64
#define KTOP 20
#define CAP 512
#define NT 256
#define NEGF 3.4e38f
#define THR0 2.2f

__device__ __forceinline__ unsigned f2key(float x) {
    unsigned u = __float_as_uint(x);
    return (u & 0x80000000u) ? ~u : (u | 0x80000000u);
}
__device__ __forceinline__ float key2f(unsigned k) {
    return __uint_as_float((k & 0x80000000u) ? (k & 0x7FFFFFFFu) : ~k);
}
__device__ __forceinline__ unsigned long long packvi(float v, int j) {
    return ((unsigned long long)f2key(v) << 32) | (unsigned)(0x7FFFFFFF - j);
}
__device__ __forceinline__ unsigned su32(const void* p) {
    unsigned a;
    asm("{ .reg .u64 t; cvta.to.shared.u64 t, %1; cvt.u32.u64 %0, t; }" : "=r"(a) : "l"(p));
    return a;
}
// mbarrier wait with HW-sleep suspend hint
__device__ __forceinline__ void mbar_wait(unsigned mb) {
    asm volatile(
        "{\n\t.reg .pred P;\n\t"
        "WAIT_%=: mbarrier.try_wait.parity.shared.b64 P, [%0], 0, 0x989680;\n\t"
        "@P bra.uni DONE_%=;\n\t"
        "bra.uni WAIT_%=;\n\t"
        "DONE_%=:\n\t}"
        :: "r"(mb) : "memory");
}

__global__ void __launch_bounds__(NT) rerank_kernel(
    const float* __restrict__ charL, const float* __restrict__ radL,
    const float* __restrict__ structL, const float* __restrict__ scL,
    const float* __restrict__ styL, const int* __restrict__ rmask,
    const int* __restrict__ slab, const int* __restrict__ sclab,
    const float* __restrict__ sig, const float* __restrict__ W1,
    const float* __restrict__ b1, const float* __restrict__ W2,
    const float* __restrict__ b2, const float* __restrict__ rwp,
    float* __restrict__ out)
{
    __shared__ __align__(128) float4 srow4[NV];     // TMA-loaded middle of the row
    __shared__ float shHT[8];                        // head [0..3], tail [4..7]
    __shared__ __align__(8) unsigned long long s_mbar;
    __shared__ unsigned long long cpack[CAP];
    __shared__ float rps[RDIM];
    __shared__ __align__(16) float4 wpack[HDIM * 2]; // {W1[0..3][j]} {W1[4..5][j],b1[j],W2[j]}
    __shared__ float sprob[SDIM], predn[STDIM];
    __shared__ float feat6[KTOP][6];
    __shared__ int tIdx[KTOP];
    __shared__ float tVal[KTOP];
    __shared__ float reds[8], redt[8], redm[8];
    __shared__ unsigned long long red64[8];
    __shared__ unsigned long long s_prev;
    __shared__ float s_sum, s_shift, s_total, s_b2, s_rw;
    __shared__ int s_ncand, s_spred;

    float* srow = (float*)srow4;
    const int b = blockIdx.x;
    const int tid = threadIdx.x, lane = tid & 31, wid = tid >> 5;

    const float* row = charL + (size_t)b * CDIM;
    float* orow = out + (size_t)b * CDIM;
    const int h = (4 - (int)(((size_t)row >> 2) & 3)) & 3;
    const int tl = 3 - h;
    const int ho = (4 - (int)(((size_t)orow >> 2) & 3)) & 3;

    // ---- init: packed weights + mbarrier ----
    if (tid < HDIM) {
        float4 a, bb;
        a.x = W1[tid]; a.y = W1[HDIM + tid]; a.z = W1[2 * HDIM + tid]; a.w = W1[3 * HDIM + tid];
        bb.x = W1[4 * HDIM + tid]; bb.y = W1[5 * HDIM + tid]; bb.z = b1[tid]; bb.w = W2[tid];
        wpack[tid * 2] = a; wpack[tid * 2 + 1] = bb;
    }
    if (tid == 0) {
        s_b2 = b2[0]; s_rw = rwp[0]; s_ncand = 0; s_shift = 0.f;
        asm volatile("mbarrier.init.shared.b64 [%0], 1;" :: "r"(su32(&s_mbar)) : "memory");
    }
    __syncthreads();

    // ---- issue TMA bulk load of the aligned middle ----
    if (tid == 0) {
        unsigned mb = su32(&s_mbar);
        asm volatile("mbarrier.arrive.expect_tx.shared.b64 _, [%0], %1;"
                     :: "r"(mb), "r"(NV * 16) : "memory");
        asm volatile("cp.async.bulk.shared::cta.global.mbarrier::complete_tx::bytes "
                     "[%0], [%1], %2, [%3];"
                     :: "r"(su32(srow4)), "l"(row + h), "r"(NV * 16), "r"(mb) : "memory");
    }

    // ---- head/tail scalars: load + copy-out + stash in smem ----
    float seHT = 0.f;
    if (wid == 0 && lane < h) {
        float v = row[lane]; shHT[lane] = v; orow[lane] = v; seHT = __expf(v);
    }
    if (wid == 1 && lane < tl) {
        int j = h + 4 * NV + lane;
        float v = row[j]; shHT[4 + lane] = v; orow[j] = v; seHT = __expf(v);
    }

    // ---- radical sigmoid + total (overlaps TMA flight) ----
    float tp = 0.f;
    if (tid < RDIM) {
        float p = 1.f / (1.f + __expf(-radL[(size_t)b * RDIM + tid]));
        rps[tid] = p; tp = p;
    }
    // side tasks on distinct warps
    if (tid == 65) {
        const float* st = structL + (size_t)b * SDIM;
        float m = st[0]; float e[SDIM];
        for (int i = 1; i < SDIM; i++) m = fmaxf(m, st[i]);
        float s = 0.f;
        for (int i = 0; i < SDIM; i++) { e[i] = __expf(st[i] - m); s += e[i]; }
        float inv = 1.f / s;
        for (int i = 0; i < SDIM; i++) sprob[i] = e[i] * inv;
    }
    if (tid == 97) {
        const float* sc = scL + (size_t)b * SCBDIM;
        float m = sc[0]; int mi = 0;
        for (int i = 1; i < SCBDIM; i++) { float vv = sc[i]; if (vv > m) { m = vv; mi = i; } }
        s_spred = mi;
    }
    if (tid == 129) {
        const float* sy = styL + (size_t)b * STDIM;
        float vv[STDIM]; float n2 = 0.f;
        for (int i = 0; i < STDIM; i++) { vv[i] = sy[i]; n2 += vv[i] * vv[i]; }
        float n = fmaxf(sqrtf(n2), 1e-12f);
        for (int i = 0; i < STDIM; i++) predn[i] = vv[i] / n;
    }

    // ---- wait for TMA load completion ----
    mbar_wait(su32(&s_mbar));

    // ---- fused sweep: unshifted expsum + order-free threshold collect ----
    float se = seHT;
    const float t0 = THR0;
    #pragma unroll
    for (int u = 0; u < 4; u++) {
        int i = tid + u * NT;
        float4 w;
        if (u < 3 || i < NV) {
            w = srow4[i];
            se += __expf(w.x) + __expf(w.y) + __expf(w.z) + __expf(w.w);
        } else { w.x = w.y = w.z = w.w = -NEGF; }
        int c = (w.x >= t0) + (w.y >= t0) + (w.z >= t0) + (w.w >= t0);
        if (c) {
            int pos = atomicAdd(&s_ncand, c);
            int j0 = h + 4 * i;
            if (w.x >= t0) { if (pos < CAP) cpack[pos] = packvi(w.x, j0); pos++; }
            if (w.y >= t0) { if (pos < CAP) cpack[pos] = packvi(w.y, j0 + 1); pos++; }
            if (w.z >= t0) { if (pos < CAP) cpack[pos] = packvi(w.z, j0 + 2); pos++; }
            if (w.w >= t0) { if (pos < CAP) cpack[pos] = packvi(w.w, j0 + 3); }
        }
    }
    // head/tail candidates
    if (wid == 0 && lane < h) {
        float v = shHT[lane];
        if (v >= t0) { int pos = atomicAdd(&s_ncand, 1); if (pos < CAP) cpack[pos] = packvi(v, lane); }
    }
    if (wid == 1 && lane < tl) {
        float v = shHT[4 + lane];
        if (v >= t0) { int pos = atomicAdd(&s_ncand, 1); if (pos < CAP) cpack[pos] = packvi(v, h + 4 * NV + lane); }
    }
    #pragma unroll
    for (int o = 16; o; o >>= 1) {
        se += __shfl_xor_sync(~0u, se, o);
        tp += __shfl_xor_sync(~0u, tp, o);
    }
    if (lane == 0) { reds[wid] = se; redt[wid] = tp; }
    __syncthreads();
    if (tid == 0) {
        float ss = 0.f, tt = 0.f;
        for (int w = 0; w < 8; w++) { ss += reds[w]; tt += redt[w]; }
        s_sum = ss; s_total = tt;
    }
    __syncthreads();

    // ---- guard: expsum overflow/underflow (never taken for sane logits) ----
    if (isinf(s_sum) || isnan(s_sum) || s_sum < 1e-30f) {
        float mx = -NEGF;
        for (int k = tid; k < 4 * NV; k += NT) mx = fmaxf(mx, srow[k]);
        if (tid < h) mx = fmaxf(mx, shHT[tid]);
        if (tid >= 32 && tid - 32 < tl) mx = fmaxf(mx, shHT[4 + tid - 32]);
        #pragma unroll
        for (int o = 16; o; o >>= 1) mx = fmaxf(mx, __shfl_xor_sync(~0u, mx, o));
        if (lane == 0) redm[wid] = mx;
        __syncthreads();
        if (tid == 0) {
            float m = redm[0];
            for (int w = 1; w < 8; w++) m = fmaxf(m, redm[w]);
            s_shift = m;
        }
        __syncthreads();
        const float shv = s_shift;
        float se2 = 0.f;
        for (int k = tid; k < 4 * NV; k += NT) se2 += __expf(srow[k] - shv);
        if (tid < h) se2 += __expf(shHT[tid] - shv);
        if (tid >= 32 && tid - 32 < tl) se2 += __expf(shHT[4 + tid - 32] - shv);
        #pragma unroll
        for (int o = 16; o; o >>= 1) se2 += __shfl_xor_sync(~0u, se2, o);
        if (lane == 0) reds[wid] = se2;
        __syncthreads();
        if (tid == 0) { float ss = 0.f; for (int w = 0; w < 8; w++) ss += reds[w]; s_sum = ss; }
        __syncthreads();
    }

    // ---- retry with lower threshold (rare) ----
    int nc = s_ncand;
    float t = t0;
    while (nc < KTOP) {
        __syncthreads();
        if (tid == 0) s_ncand = 0;
        t -= 1.5f;
        __syncthreads();
        for (int base_k = 0; base_k < 4 * NV; base_k += NT) {
            int k = base_k + tid;
            float v = (k < 4 * NV) ? srow[k] : -NEGF;
            if (v >= t) {
                int pos = atomicAdd(&s_ncand, 1);
                if (pos < CAP) cpack[pos] = packvi(v, h + k);
            }
        }
        if (wid == 0 && lane < h) {
            float v = shHT[lane];
            if (v >= t) { int pos = atomicAdd(&s_ncand, 1); if (pos < CAP) cpack[pos] = packvi(v, lane); }
        }
        if (wid == 1 && lane < tl) {
            float v = shHT[4 + lane];
            if (v >= t) { int pos = atomicAdd(&s_ncand, 1); if (pos < CAP) cpack[pos] = packvi(v, h + 4 * NV + lane); }
        }
        __syncthreads();
        nc = s_ncand;
    }

    // ---- selection: parallel rank (ties: lower index wins, encoded in pack) ----
    if (nc <= NT) {
        if (tid - lane < nc) {
            unsigned long long p0 = (tid < nc) ? cpack[tid] : 0ull;
            int r0 = 0;
            #pragma unroll 4
            for (int j = 0; j < nc; j++) r0 += (cpack[j] > p0);
            if (tid < nc && r0 < KTOP) {
                tIdx[r0] = 0x7FFFFFFF - (int)(p0 & 0xFFFFFFFFu);
                tVal[r0] = key2f((unsigned)(p0 >> 32));
            }
        }
    } else if (nc <= CAP) {
        unsigned long long p0 = cpack[tid];
        unsigned long long p1 = (tid + NT < nc) ? cpack[tid + NT] : 0ull;
        int r0 = 0, r1 = 0;
        for (int j = 0; j < nc; j++) {
            unsigned long long q = cpack[j];
            r0 += (q > p0); r1 += (q > p1);
        }
        if (r0 < KTOP) {
            tIdx[r0] = 0x7FFFFFFF - (int)(p0 & 0xFFFFFFFFu);
            tVal[r0] = key2f((unsigned)(p0 >> 32));
        }
        if (tid + NT < nc && r1 < KTOP) {
            tIdx[r1] = 0x7FFFFFFF - (int)(p1 & 0xFFFFFFFFu);
            tVal[r1] = key2f((unsigned)(p1 >> 32));
        }
    } else {
        // robust fallback (adversarial only): 20 rounds of block argmax over smem
        unsigned long long prev = ~0ull;
        for (int k = 0; k < KTOP; k++) {
            unsigned long long best = 0ull;
            for (int kk = tid; kk < 4 * NV; kk += NT) {
                unsigned long long p = packvi(srow[kk], h + kk);
                if (p < prev && p > best) best = p;
            }
            if (tid < h) { unsigned long long p = packvi(shHT[tid], tid); if (p < prev && p > best) best = p; }
            if (tid >= 32 && tid - 32 < tl) {
                unsigned long long p = packvi(shHT[4 + tid - 32], h + 4 * NV + tid - 32);
                if (p < prev && p > best) best = p;
            }
            #pragma unroll
            for (int o = 16; o; o >>= 1) {
                unsigned long long q = __shfl_xor_sync(~0u, best, o);
                if (q > best) best = q;
            }
            if (lane == 0) red64[wid] = best;
            __syncthreads();
            if (tid == 0) {
                unsigned long long m = red64[0];
                for (int w = 1; w < 8; w++) if (red64[w] > m) m = red64[w];
                tIdx[k] = 0x7FFFFFFF - (int)(m & 0xFFFFFFFFu);
                tVal[k] = key2f((unsigned)(m >> 32));
                s_prev = m;
            }
            __syncthreads();
            prev = s_prev;
        }
    }
    __syncthreads();

    // ---- features: 8-lane groups for radical dot; threads 160.. do scalars ----
    const int g = tid >> 3, gl = tid & 7;
    const float total = s_total;
    if (g < KTOP) {
        int c = tIdx[g];
        const int2* m2 = (const int2*)(rmask + (size_t)c * RDIM);
        float det = 0.f; int cnt = 0;
        for (int r = gl; r < RDIM / 2; r += 8) {
            int2 mm = m2[r];
            det = fmaf((float)mm.x, rps[2 * r], det);
            det = fmaf((float)mm.y, rps[2 * r + 1], det);
            cnt += mm.x + mm.y;
        }
        #pragma unroll
        for (int o = 4; o; o >>= 1) {
            det += __shfl_xor_sync(~0u, det, o);
            cnt += __shfl_xor_sync(~0u, cnt, o);
        }
        if (gl == 0) {
            feat6[g][0] = det / fmaxf((float)cnt, 1.f);
            feat6[g][1] = (total - det) / fmaxf(total, 1e-6f);
        }
    }
    if (tid >= 160 && tid < 160 + KTOP) {
        int k = tid - 160;
        int c = tIdx[k];
        feat6[k][2] = sprob[slab[c]];
        feat6[k][3] = fabsf((float)(s_spred - sclab[c])) * (1.f / 29.f);
        const float* s6 = sig + (size_t)c * STDIM;
        float n2 = 0.f, dd = 0.f;
        #pragma unroll
        for (int i = 0; i < STDIM; i++) {
            float vv = s6[i];
            n2 += vv * vv;
            dd += predn[i] * vv;
        }
        float nrm = sqrtf(n2);
        feat6[k][4] = (nrm > 1e-6f) ? dd / fmaxf(nrm, 1e-12f) : 0.f;
        feat6[k][5] = __expf(tVal[k] - s_shift) / s_sum;
    }
    __syncthreads();

    // ---- MLP 6->64->1 via packed weights; patch scores into smem/global ----
    if (g < KTOP) {
        float f0 = feat6[g][0], f1 = feat6[g][1], f2 = feat6[g][2];
        float f3 = feat6[g][3], f4 = feat6[g][4], f5 = feat6[g][5];
        float score = 0.f;
        #pragma unroll
        for (int u = 0; u < 8; u++) {
            int j = gl + u * 8;
            float4 a = wpack[j * 2], bb = wpack[j * 2 + 1];
            float hh = bb.z + f0 * a.x + f1 * a.y + f2 * a.z + f3 * a.w
                     + f4 * bb.x + f5 * bb.y;
            score += fmaxf(hh, 0.f) * bb.w;
        }
        #pragma unroll
        for (int o = 4; o; o >>= 1) score += __shfl_xor_sync(~0u, score, o);
        if (gl == 0) {
            int idx = tIdx[g];
            float comb = tVal[g] + s_rw * (score + s_b2);
            if (idx >= h && idx < h + 4 * NV) srow[idx - h] = comb;
            else orow[idx] = comb;       // head/tail patch (ordered after copy by barriers)
        }
    }
    __syncthreads();

    // ---- write the middle back: TMA bulk store (or scalar fallback) ----
    if (ho == h) {
        if (tid == 0) {
            asm volatile("fence.proxy.async.shared::cta;" ::: "memory");
            asm volatile("cp.async.bulk.global.shared::cta.bulk_group [%0], [%1], %2;"
                         :: "l"(orow + h), "r"(su32(srow4)), "r"(NV * 16) : "memory");
            asm volatile("cp.async.bulk.commit_group;" ::: "memory");
            asm volatile("cp.async.bulk.wait_group 0;" ::: "memory");
        }
    } else {
        // out row misaligned vs in row (not expected with cudaMalloc bases)
        for (int k = tid; k < 4 * NV; k += NT) orow[h + k] = srow[k];
    }
}

extern "C" void kernel_launch(void* const* d_in, const int* in_sizes, int n_in,
                              void* d_out, int out_size) {
    (void)n_in; (void)out_size;
    int Bn = in_sizes[0] / CDIM;
    rerank_kernel<<<Bn, NT>>>(
        (const float*)d_in[0],  (const float*)d_in[1],  (const float*)d_in[2],
        (const float*)d_in[3],  (const float*)d_in[4],  (const int*)d_in[5],
        (const int*)d_in[6],    (const int*)d_in[7],    (const float*)d_in[8],
        (const float*)d_in[9],  (const float*)d_in[10], (const float*)d_in[11],
        (const float*)d_in[12], (const float*)d_in[13], (float*)d_out);
}

// round 16
// speedup vs baseline: 1.3493x; 1.0495x over previous
#include <cuda_runtime.h>

#define CDIM 3755
#define NV 938              // (CDIM - h) >> 2 == 938 for every h in 0..3
#define RDIM 214
#define SDIM 13
#define SCBDIM 30
#define STDIM 6
#define HDIM 64
#define KTOP 20
#define CAP 512
#define NT 256
#define NEGF 3.4e38f
#define THR0 2.2f

__device__ __forceinline__ unsigned f2key(float x) {
    unsigned u = __float_as_uint(x);
    return (u & 0x80000000u) ? ~u : (u | 0x80000000u);
}
__device__ __forceinline__ float key2f(unsigned k) {
    return __uint_as_float((k & 0x80000000u) ? (k & 0x7FFFFFFFu) : ~k);
}
__device__ __forceinline__ unsigned long long packvi(float v, int j) {
    return ((unsigned long long)f2key(v) << 32) | (unsigned)(0x7FFFFFFF - j);
}
__device__ __forceinline__ unsigned su32(const void* p) {
    unsigned a;
    asm("{ .reg .u64 t; cvta.to.shared.u64 t, %1; cvt.u32.u64 %0, t; }" : "=r"(a) : "l"(p));
    return a;
}

__global__ void __launch_bounds__(NT) rerank_kernel(
    const float* __restrict__ charL, const float* __restrict__ radL,
    const float* __restrict__ structL, const float* __restrict__ scL,
    const float* __restrict__ styL, const int* __restrict__ rmask,
    const int* __restrict__ slab, const int* __restrict__ sclab,
    const float* __restrict__ sig, const float* __restrict__ W1,
    const float* __restrict__ b1, const float* __restrict__ W2,
    const float* __restrict__ b2, const float* __restrict__ rwp,
    float* __restrict__ out)
{
    __shared__ __align__(128) float4 srow4[NV];     // TMA-loaded middle of the row
    __shared__ float shHT[8];                        // head [0..3], tail [4..7]
    __shared__ __align__(8) unsigned long long s_mbar;
    __shared__ unsigned long long cpack[CAP];
    __shared__ float rps[RDIM];
    __shared__ float w1s[6 * HDIM], b1sh[HDIM], w2sh[HDIM];
    __shared__ float sprob[SDIM], predn[STDIM];
    __shared__ float feat6[KTOP][6];
    __shared__ int tIdx[KTOP];
    __shared__ float tVal[KTOP];
    __shared__ float reds[8], redt[8], redm[8];
    __shared__ unsigned long long red64[8];
    __shared__ unsigned long long s_prev;
    __shared__ float s_sum, s_shift, s_total, s_b2, s_rw;
    __shared__ int s_ncand, s_spred;

    float* srow = (float*)srow4;
    const int b = blockIdx.x;
    const int tid = threadIdx.x, lane = tid & 31, wid = tid >> 5;

    const float* row = charL + (size_t)b * CDIM;
    float* orow = out + (size_t)b * CDIM;
    const int h = (4 - (int)(((size_t)row >> 2) & 3)) & 3;
    const int tl = 3 - h;
    const int ho = (4 - (int)(((size_t)orow >> 2) & 3)) & 3;

    // ---- init: weights + mbarrier ----
    for (int i = tid; i < 6 * HDIM; i += NT) w1s[i] = W1[i];
    if (tid < HDIM) { b1sh[tid] = b1[tid]; w2sh[tid] = W2[tid]; }
    if (tid == 0) {
        s_b2 = b2[0]; s_rw = rwp[0]; s_ncand = 0; s_shift = 0.f;
        asm volatile("mbarrier.init.shared.b64 [%0], 1;" :: "r"(su32(&s_mbar)) : "memory");
    }
    __syncthreads();

    // ---- issue TMA bulk load of the aligned middle ----
    if (tid == 0) {
        unsigned mb = su32(&s_mbar);
        asm volatile("mbarrier.arrive.expect_tx.shared.b64 _, [%0], %1;"
                     :: "r"(mb), "r"(NV * 16) : "memory");
        asm volatile("cp.async.bulk.shared::cta.global.mbarrier::complete_tx::bytes "
                     "[%0], [%1], %2, [%3];"
                     :: "r"(su32(srow4)), "l"(row + h), "r"(NV * 16), "r"(mb) : "memory");
    }

    // ---- head/tail scalars: load + copy-out + stash in smem ----
    float seHT = 0.f;
    if (wid == 0 && lane < h) {
        float v = row[lane]; shHT[lane] = v; orow[lane] = v; seHT = __expf(v);
    }
    if (wid == 1 && lane < tl) {
        int j = h + 4 * NV + lane;
        float v = row[j]; shHT[4 + lane] = v; orow[j] = v; seHT = __expf(v);
    }

    // ---- radical sigmoid + total (overlaps TMA flight) ----
    float tp = 0.f;
    if (tid < RDIM) {
        float p = 1.f / (1.f + __expf(-radL[(size_t)b * RDIM + tid]));
        rps[tid] = p; tp = p;
    }
    // side tasks on distinct warps
    if (tid == 65) {
        const float* st = structL + (size_t)b * SDIM;
        float m = st[0]; float e[SDIM];
        for (int i = 1; i < SDIM; i++) m = fmaxf(m, st[i]);
        float s = 0.f;
        for (int i = 0; i < SDIM; i++) { e[i] = __expf(st[i] - m); s += e[i]; }
        float inv = 1.f / s;
        for (int i = 0; i < SDIM; i++) sprob[i] = e[i] * inv;
    }
    if (tid == 97) {
        const float* sc = scL + (size_t)b * SCBDIM;
        float m = sc[0]; int mi = 0;
        for (int i = 1; i < SCBDIM; i++) { float vv = sc[i]; if (vv > m) { m = vv; mi = i; } }
        s_spred = mi;
    }
    if (tid == 129) {
        const float* sy = styL + (size_t)b * STDIM;
        float vv[STDIM]; float n2 = 0.f;
        for (int i = 0; i < STDIM; i++) { vv[i] = sy[i]; n2 += vv[i] * vv[i]; }
        float n = fmaxf(sqrtf(n2), 1e-12f);
        for (int i = 0; i < STDIM; i++) predn[i] = vv[i] / n;
    }

    // ---- wait for TMA load completion ----
    {
        unsigned mb = su32(&s_mbar);
        unsigned done;
        do {
            asm volatile(
                "{\n\t.reg .pred p;\n\t"
                "mbarrier.try_wait.parity.shared.b64 p, [%1], 0;\n\t"
                "selp.b32 %0, 1, 0, p;\n\t}"
                : "=r"(done) : "r"(mb) : "memory");
        } while (!done);
    }

    // ---- fused sweep: unshifted expsum + max-prefiltered threshold collect ----
    float se = seHT;
    const float t0 = THR0;
    #pragma unroll
    for (int u = 0; u < 4; u++) {
        int i = tid + u * NT;
        float4 w;
        if (u < 3 || i < NV) {
            w = srow4[i];
            se += __expf(w.x) + __expf(w.y) + __expf(w.z) + __expf(w.w);
        } else { w.x = w.y = w.z = w.w = -NEGF; }
        float m4 = fmaxf(fmaxf(w.x, w.y), fmaxf(w.z, w.w));
        if (m4 >= t0) {   // rare (~5% of float4s): full per-element path
            int c = (w.x >= t0) + (w.y >= t0) + (w.z >= t0) + (w.w >= t0);
            int pos = atomicAdd(&s_ncand, c);
            int j0 = h + 4 * i;
            if (w.x >= t0) { if (pos < CAP) cpack[pos] = packvi(w.x, j0); pos++; }
            if (w.y >= t0) { if (pos < CAP) cpack[pos] = packvi(w.y, j0 + 1); pos++; }
            if (w.z >= t0) { if (pos < CAP) cpack[pos] = packvi(w.z, j0 + 2); pos++; }
            if (w.w >= t0) { if (pos < CAP) cpack[pos] = packvi(w.w, j0 + 3); }
        }
    }
    // head/tail candidates
    if (wid == 0 && lane < h) {
        float v = shHT[lane];
        if (v >= t0) { int pos = atomicAdd(&s_ncand, 1); if (pos < CAP) cpack[pos] = packvi(v, lane); }
    }
    if (wid == 1 && lane < tl) {
        float v = shHT[4 + lane];
        if (v >= t0) { int pos = atomicAdd(&s_ncand, 1); if (pos < CAP) cpack[pos] = packvi(v, h + 4 * NV + lane); }
    }
    #pragma unroll
    for (int o = 16; o; o >>= 1) {
        se += __shfl_xor_sync(~0u, se, o);
        tp += __shfl_xor_sync(~0u, tp, o);
    }
    if (lane == 0) { reds[wid] = se; redt[wid] = tp; }
    __syncthreads();
    if (tid == 0) {
        float ss = 0.f, tt = 0.f;
        for (int w = 0; w < 8; w++) { ss += reds[w]; tt += redt[w]; }
        s_sum = ss; s_total = tt;
    }
    __syncthreads();

    // ---- guard: expsum overflow/underflow (never taken for sane logits) ----
    if (isinf(s_sum) || isnan(s_sum) || s_sum < 1e-30f) {
        float mx = -NEGF;
        for (int k = tid; k < 4 * NV; k += NT) mx = fmaxf(mx, srow[k]);
        if (tid < h) mx = fmaxf(mx, shHT[tid]);
        if (tid >= 32 && tid - 32 < tl) mx = fmaxf(mx, shHT[4 + tid - 32]);
        #pragma unroll
        for (int o = 16; o; o >>= 1) mx = fmaxf(mx, __shfl_xor_sync(~0u, mx, o));
        if (lane == 0) redm[wid] = mx;
        __syncthreads();
        if (tid == 0) {
            float m = redm[0];
            for (int w = 1; w < 8; w++) m = fmaxf(m, redm[w]);
            s_shift = m;
        }
        __syncthreads();
        const float shv = s_shift;
        float se2 = 0.f;
        for (int k = tid; k < 4 * NV; k += NT) se2 += __expf(srow[k] - shv);
        if (tid < h) se2 += __expf(shHT[tid] - shv);
        if (tid >= 32 && tid - 32 < tl) se2 += __expf(shHT[4 + tid - 32] - shv);
        #pragma unroll
        for (int o = 16; o; o >>= 1) se2 += __shfl_xor_sync(~0u, se2, o);
        if (lane == 0) reds[wid] = se2;
        __syncthreads();
        if (tid == 0) { float ss = 0.f; for (int w = 0; w < 8; w++) ss += reds[w]; s_sum = ss; }
        __syncthreads();
    }

    // ---- retry with lower threshold (rare) ----
    int nc = s_ncand;
    float t = t0;
    while (nc < KTOP) {
        __syncthreads();
        if (tid == 0) s_ncand = 0;
        t -= 1.5f;
        __syncthreads();
        for (int base_k = 0; base_k < 4 * NV; base_k += NT) {
            int k = base_k + tid;
            float v = (k < 4 * NV) ? srow[k] : -NEGF;
            if (v >= t) {
                int pos = atomicAdd(&s_ncand, 1);
                if (pos < CAP) cpack[pos] = packvi(v, h + k);
            }
        }
        if (wid == 0 && lane < h) {
            float v = shHT[lane];
            if (v >= t) { int pos = atomicAdd(&s_ncand, 1); if (pos < CAP) cpack[pos] = packvi(v, lane); }
        }
        if (wid == 1 && lane < tl) {
            float v = shHT[4 + lane];
            if (v >= t) { int pos = atomicAdd(&s_ncand, 1); if (pos < CAP) cpack[pos] = packvi(v, h + 4 * NV + lane); }
        }
        __syncthreads();
        nc = s_ncand;
    }

    // ---- selection: parallel rank (ties: lower index wins, encoded in pack) ----
    if (nc <= NT) {
        if (tid - lane < nc) {
            unsigned long long p0 = (tid < nc) ? cpack[tid] : 0ull;
            int r0 = 0;
            #pragma unroll 4
            for (int j = 0; j < nc; j++) r0 += (cpack[j] > p0);
            if (tid < nc && r0 < KTOP) {
                tIdx[r0] = 0x7FFFFFFF - (int)(p0 & 0xFFFFFFFFu);
                tVal[r0] = key2f((unsigned)(p0 >> 32));
            }
        }
    } else if (nc <= CAP) {
        unsigned long long p0 = cpack[tid];
        unsigned long long p1 = (tid + NT < nc) ? cpack[tid + NT] : 0ull;
        int r0 = 0, r1 = 0;
        for (int j = 0; j < nc; j++) {
            unsigned long long q = cpack[j];
            r0 += (q > p0); r1 += (q > p1);
        }
        if (r0 < KTOP) {
            tIdx[r0] = 0x7FFFFFFF - (int)(p0 & 0xFFFFFFFFu);
            tVal[r0] = key2f((unsigned)(p0 >> 32));
        }
        if (tid + NT < nc && r1 < KTOP) {
            tIdx[r1] = 0x7FFFFFFF - (int)(p1 & 0xFFFFFFFFu);
            tVal[r1] = key2f((unsigned)(p1 >> 32));
        }
    } else {
        // robust fallback (adversarial only): 20 rounds of block argmax over smem
        unsigned long long prev = ~0ull;
        for (int k = 0; k < KTOP; k++) {
            unsigned long long best = 0ull;
            for (int kk = tid; kk < 4 * NV; kk += NT) {
                unsigned long long p = packvi(srow[kk], h + kk);
                if (p < prev && p > best) best = p;
            }
            if (tid < h) { unsigned long long p = packvi(shHT[tid], tid); if (p < prev && p > best) best = p; }
            if (tid >= 32 && tid - 32 < tl) {
                unsigned long long p = packvi(shHT[4 + tid - 32], h + 4 * NV + tid - 32);
                if (p < prev && p > best) best = p;
            }
            #pragma unroll
            for (int o = 16; o; o >>= 1) {
                unsigned long long q = __shfl_xor_sync(~0u, best, o);
                if (q > best) best = q;
            }
            if (lane == 0) red64[wid] = best;
            __syncthreads();
            if (tid == 0) {
                unsigned long long m = red64[0];
                for (int w = 1; w < 8; w++) if (red64[w] > m) m = red64[w];
                tIdx[k] = 0x7FFFFFFF - (int)(m & 0xFFFFFFFFu);
                tVal[k] = key2f((unsigned)(m >> 32));
                s_prev = m;
            }
            __syncthreads();
            prev = s_prev;
        }
    }
    __syncthreads();

    // ---- features: 8-lane groups for radical dot; threads 160.. do scalars ----
    const int g = tid >> 3, gl = tid & 7;
    const float total = s_total;
    if (g < KTOP) {
        int c = tIdx[g];
        const int2* m2 = (const int2*)(rmask + (size_t)c * RDIM);
        float det = 0.f; int cnt = 0;
        for (int r = gl; r < RDIM / 2; r += 8) {
            int2 mm = m2[r];
            det = fmaf((float)mm.x, rps[2 * r], det);
            det = fmaf((float)mm.y, rps[2 * r + 1], det);
            cnt += mm.x + mm.y;
        }
        #pragma unroll
        for (int o = 4; o; o >>= 1) {
            det += __shfl_xor_sync(~0u, det, o);
            cnt += __shfl_xor_sync(~0u, cnt, o);
        }
        if (gl == 0) {
            feat6[g][0] = det / fmaxf((float)cnt, 1.f);
            feat6[g][1] = (total - det) / fmaxf(total, 1e-6f);
        }
    }
    if (tid >= 160 && tid < 160 + KTOP) {
        int k = tid - 160;
        int c = tIdx[k];
        feat6[k][2] = sprob[slab[c]];
        feat6[k][3] = fabsf((float)(s_spred - sclab[c])) * (1.f / 29.f);
        const float* s6 = sig + (size_t)c * STDIM;
        float n2 = 0.f, dd = 0.f;
        #pragma unroll
        for (int i = 0; i < STDIM; i++) {
            float vv = s6[i];
            n2 += vv * vv;
            dd += predn[i] * vv;
        }
        float nrm = sqrtf(n2);
        feat6[k][4] = (nrm > 1e-6f) ? dd / fmaxf(nrm, 1e-12f) : 0.f;
        feat6[k][5] = __expf(tVal[k] - s_shift) / s_sum;
    }
    __syncthreads();

    // ---- MLP 6->64->1; patch scores into smem row (or global for head/tail) ----
    if (g < KTOP) {
        float f0 = feat6[g][0], f1 = feat6[g][1], f2 = feat6[g][2];
        float f3 = feat6[g][3], f4 = feat6[g][4], f5 = feat6[g][5];
        float score = 0.f;
        #pragma unroll
        for (int u = 0; u < 8; u++) {
            int j = gl + u * 8;
            float hh = b1sh[j] + f0 * w1s[j] + f1 * w1s[HDIM + j]
                     + f2 * w1s[2 * HDIM + j] + f3 * w1s[3 * HDIM + j]
                     + f4 * w1s[4 * HDIM + j] + f5 * w1s[5 * HDIM + j];
            score += fmaxf(hh, 0.f) * w2sh[j];
        }
        #pragma unroll
        for (int o = 4; o; o >>= 1) score += __shfl_xor_sync(~0u, score, o);
        if (gl == 0) {
            int idx = tIdx[g];
            float comb = tVal[g] + s_rw * (score + s_b2);
            if (idx >= h && idx < h + 4 * NV) srow[idx - h] = comb;
            else orow[idx] = comb;       // head/tail patch (ordered after copy by barriers)
        }
    }
    __syncthreads();

    // ---- write the middle back: TMA bulk store (or scalar fallback) ----
    if (ho == h) {
        if (tid == 0) {
            asm volatile("fence.proxy.async.shared::cta;" ::: "memory");
            asm volatile("cp.async.bulk.global.shared::cta.bulk_group [%0], [%1], %2;"
                         :: "l"(orow + h), "r"(su32(srow4)), "r"(NV * 16) : "memory");
            asm volatile("cp.async.bulk.commit_group;" ::: "memory");
            asm volatile("cp.async.bulk.wait_group 0;" ::: "memory");
        }
    } else {
        // out row misaligned vs in row (not expected with cudaMalloc bases)
        for (int k = tid; k < 4 * NV; k += NT) orow[h + k] = srow[k];
    }
}

extern "C" void kernel_launch(void* const* d_in, const int* in_sizes, int n_in,
                              void* d_out, int out_size) {
    (void)n_in; (void)out_size;
    int Bn = in_sizes[0] / CDIM;
    rerank_kernel<<<Bn, NT>>>(
        (const float*)d_in[0],  (const float*)d_in[1],  (const float*)d_in[2],
        (const float*)d_in[3],  (const float*)d_in[4],  (const int*)d_in[5],
        (const int*)d_in[6],    (const int*)d_in[7],    (const float*)d_in[8],
        (const float*)d_in[9],  (const float*)d_in[10], (const float*)d_in[11],
        (const float*)d_in[12], (const float*)d_in[13], (float*)d_out);
}